// round 4
// baseline (speedup 1.0000x reference)
#include <cuda_runtime.h>
#include <cuda_bf16.h>

// AddingGaussianBlur: x (64,512,512,3) f32, stds (64,) f32 -> out f32.
//
// Separable (reference's 3x3 kernel depends only on column index):
//   vertical  : unweighted 3-row sum (zero padded)
//   horizontal: [a, 1, a] / (3*(1+2a)),  a = exp(-1/s^2), s = 3*std[b]
//
// R4: NO shared memory, NO barriers. Each thread owns float4 chunk t of every
// row in its band and redundantly loads neighbor chunks t-1 / t+1 (same cache
// lines the warp already fetches -> L1 hits, DRAM traffic unchanged). The
// 3-row x 3-chunk window rolls in registers; the horizontal +-3 taps are
// assembled locally. Pure streaming: latency hidden by 3 outstanding
// LDG.128/thread with no sync coupling.

#define H       512
#define ROWW    1536            // 512 * 3 floats per image row
#define NT      384             // 384 threads x float4 = one row
#define RPB     16              // rows per block band

__global__ __launch_bounds__(NT)
void gauss_blur_kernel(const float* __restrict__ x,
                       const float* __restrict__ stds,
                       float* __restrict__ out)
{
    const int b  = blockIdx.y;
    const int i0 = blockIdx.x * RPB;
    const int t  = threadIdx.x;

    const float s   = stds[b] * 3.0f;
    const float a   = expf(-1.0f / (s * s));
    const float inv = 1.0f / (3.0f * (1.0f + 2.0f * a));

    const float* __restrict__ xb = x   + (size_t)b * H * ROWW;
    float*       __restrict__ ob = out + (size_t)b * H * ROWW;

    const bool hasL = (t > 0);
    const bool hasR = (t < NT - 1);
    const float4 Z  = make_float4(0.0f, 0.0f, 0.0f, 0.0f);

    // Load chunks t-1, t, t+1 of row gi (zeros out of range).
    auto ld3 = [&](int gi, float4& L, float4& C, float4& R) {
        if ((unsigned)gi < (unsigned)H) {
            const float4* p = reinterpret_cast<const float4*>(xb + (size_t)gi * ROWW) + t;
            C = p[0];
            L = hasL ? p[-1] : Z;
            R = hasR ? p[ 1] : Z;
        } else {
            L = Z; C = Z; R = Z;
        }
    };

    // rolling window: rows gi-1 (m), gi (c), gi+1 (p), each 3 chunks
    float4 mL, mC, mR, cL, cC, cR, pL, pC, pR;
    ld3(i0 - 1, mL, mC, mR);
    ld3(i0,     cL, cC, cR);
    ld3(i0 + 1, pL, pC, pR);

    #pragma unroll 4
    for (int r = 0; r < RPB; r++) {
        const int gi = i0 + r;

        // prefetch row gi+2 (independent of everything below)
        float4 nL, nC, nR;
        ld3(gi + 2, nL, nC, nR);

        // vertical sums: center chunk fully, neighbors only needed lanes
        float4 v;
        v.x = mC.x + cC.x + pC.x;
        v.y = mC.y + cC.y + pC.y;
        v.z = mC.z + cC.z + pC.z;
        v.w = mC.w + cC.w + pC.w;

        const float ly = mL.y + cL.y + pL.y;   // vsum[4t-3]
        const float lz = mL.z + cL.z + pL.z;   // vsum[4t-2]
        const float lw = mL.w + cL.w + pL.w;   // vsum[4t-1]
        const float rx = mR.x + cR.x + pR.x;   // vsum[4t+4]
        const float ry = mR.y + cR.y + pR.y;   // vsum[4t+5]
        const float rz = mR.z + cR.z + pR.z;   // vsum[4t+6]

        // out[e] = inv * (a*(vsum[e-3] + vsum[e+3]) + vsum[e]),  e = 4t+j
        float4 o;
        o.x = inv * (a * (ly  + v.w) + v.x);
        o.y = inv * (a * (lz  + rx ) + v.y);
        o.z = inv * (a * (lw  + ry ) + v.z);
        o.w = inv * (a * (v.x + rz ) + v.w);

        __stcs(&reinterpret_cast<float4*>(ob + (size_t)gi * ROWW)[t], o);

        // rotate window down one row
        mL = cL; mC = cC; mR = cR;
        cL = pL; cC = pC; cR = pR;
        pL = nL; pC = nC; pR = nR;
    }
}

extern "C" void kernel_launch(void* const* d_in, const int* in_sizes, int n_in,
                              void* d_out, int out_size)
{
    const float* x    = (const float*)d_in[0];
    const float* stds = (const float*)d_in[1];
    float* out        = (float*)d_out;

    dim3 grid(H / RPB, 64);   // (32, 64) = 2048 blocks
    gauss_blur_kernel<<<grid, NT>>>(x, stds, out);
}

// round 5
// speedup vs baseline: 1.0658x; 1.0658x over previous
#include <cuda_runtime.h>
#include <cuda_bf16.h>

// AddingGaussianBlur: x (64,512,512,3) f32, stds (64,) f32 -> out f32.
//
// Separable (reference's 3x3 kernel depends only on column index):
//   vertical  : unweighted 3-row sum (zero padded)
//   horizontal: [a, 1, a] / (3*(1+2a)),  a = exp(-1/s^2), s = 3*std[b]
//
// R5: barrier-free, smem-free. Each WARP owns a 128-float row segment
// (32 lanes x float4). Vertical 3-row sum rolls in registers; the +-3
// horizontal taps come from adjacent lanes via 6 SHFLs. Lanes 0/31 cover the
// warp-boundary halo with one predicated LDG.128 per row (L2-deduped against
// the neighbor warp's fetch). 1 main LDG.128 + 1 STG.128 per chunk per row.

#define H       512
#define ROWW    1536            // 512 * 3 floats per image row
#define NCHUNK  384             // float4 chunks per row
#define NT      384             // 12 warps = 12 segments = one full row
#define RPB     32              // rows per block band

__global__ __launch_bounds__(NT)
void gauss_blur_kernel(const float* __restrict__ x,
                       const float* __restrict__ stds,
                       float* __restrict__ out)
{
    const int b  = blockIdx.y;
    const int i0 = blockIdx.x * RPB;
    const int t  = threadIdx.x;
    const int l  = t & 31;
    const int ci = t;                       // chunk index within row (warp = 32 chunks)

    const float s   = stds[b] * 3.0f;
    const float a   = expf(-1.0f / (s * s));
    const float inv = 1.0f / (3.0f * (1.0f + 2.0f * a));

    const float* __restrict__ xb = x   + (size_t)b * H * ROWW;
    float*       __restrict__ ob = out + (size_t)b * H * ROWW;

    // Halo chunk: lane 0 fetches chunk ci-1, lane 31 fetches chunk ci+1.
    int  hi   = ci;
    bool hasH = false;
    if (l == 0)       { hi = ci - 1; hasH = (ci > 0); }
    else if (l == 31) { hi = ci + 1; hasH = (ci < NCHUNK - 1); }

    const float4 Z = make_float4(0.0f, 0.0f, 0.0f, 0.0f);

    // Load own chunk C and halo chunk E of row gi (zeros out of range).
    auto ld = [&](int gi, float4& C, float4& E) {
        if ((unsigned)gi < (unsigned)H) {
            const float4* p = reinterpret_cast<const float4*>(xb + (size_t)gi * ROWW);
            C = p[ci];
            E = hasH ? p[hi] : Z;
        } else {
            C = Z; E = Z;
        }
    };

    // rolling window: rows gi-1 (m), gi (c), gi+1 (p)
    float4 mC, mE, cC, cE, pC, pE;
    ld(i0 - 1, mC, mE);
    ld(i0,     cC, cE);
    ld(i0 + 1, pC, pE);

    #pragma unroll 4
    for (int r = 0; r < RPB; r++) {
        const int gi = i0 + r;

        // prefetch row gi+2
        float4 nC, nE;
        ld(gi + 2, nC, nE);

        // vertical sums
        float4 v, vE;
        v.x  = mC.x + cC.x + pC.x;
        v.y  = mC.y + cC.y + pC.y;
        v.z  = mC.z + cC.z + pC.z;
        v.w  = mC.w + cC.w + pC.w;
        vE.x = mE.x + cE.x + pE.x;
        vE.y = mE.y + cE.y + pE.y;
        vE.z = mE.z + cE.z + pE.z;
        vE.w = mE.w + cE.w + pE.w;

        // neighbor-lane vsum elements via shuffle; edge lanes use halo vE
        float ly = __shfl_up_sync(0xffffffffu, v.y, 1);     // vsum[4ci-3]
        float lz = __shfl_up_sync(0xffffffffu, v.z, 1);     // vsum[4ci-2]
        float lw = __shfl_up_sync(0xffffffffu, v.w, 1);     // vsum[4ci-1]
        float rx = __shfl_down_sync(0xffffffffu, v.x, 1);   // vsum[4ci+4]
        float ry = __shfl_down_sync(0xffffffffu, v.y, 1);   // vsum[4ci+5]
        float rz = __shfl_down_sync(0xffffffffu, v.z, 1);   // vsum[4ci+6]
        if (l == 0)  { ly = vE.y; lz = vE.z; lw = vE.w; }   // halo = chunk ci-1
        if (l == 31) { rx = vE.x; ry = vE.y; rz = vE.z; }   // halo = chunk ci+1

        // out[e] = inv * (a*(vsum[e-3] + vsum[e+3]) + vsum[e]),  e = 4ci+j
        float4 o;
        o.x = inv * (a * (ly  + v.w) + v.x);
        o.y = inv * (a * (lz  + rx ) + v.y);
        o.z = inv * (a * (lw  + ry ) + v.z);
        o.w = inv * (a * (v.x + rz ) + v.w);

        __stcs(&reinterpret_cast<float4*>(ob + (size_t)gi * ROWW)[ci], o);

        // rotate window
        mC = cC; mE = cE;
        cC = pC; cE = pE;
        pC = nC; pE = nE;
    }
}

extern "C" void kernel_launch(void* const* d_in, const int* in_sizes, int n_in,
                              void* d_out, int out_size)
{
    const float* x    = (const float*)d_in[0];
    const float* stds = (const float*)d_in[1];
    float* out        = (float*)d_out;

    dim3 grid(H / RPB, 64);   // (16, 64) = 1024 blocks
    gauss_blur_kernel<<<grid, NT>>>(x, stds, out);
}